// round 2
// baseline (speedup 1.0000x reference)
#include <cuda_runtime.h>
#include <math.h>

// Scratch for per-b AP values. Static __device__ array (no allocation).
#define MAX_B 4096
__device__ float g_ap[MAX_B];

// 100 * log2(e): sigmoid((s_j - s_i)/0.01) = 1 / (1 + 2^((s_i - s_j)*SCALE))
#define SIG_SCALE 144.26950408889634f

// One block per row b. Computes ap[b] and stores to g_ap[b].
// Shared layout: s[0..B) = scores row, s[B..2B) = target row (membership).
__global__ void __launch_bounds__(512) ap_kernel(const float* __restrict__ scores,
                                                 const float* __restrict__ target,
                                                 int B) {
    extern __shared__ float sm[];
    float* s    = sm;        // raw scores row
    float* memb = sm + B;    // target row (1.0 / 0.0)
    __shared__ float w_ratio[16];
    __shared__ float w_cnt[16];

    const int b = blockIdx.x;
    const float* __restrict__ srow = scores + (size_t)b * B;
    const float* __restrict__ trow = target + (size_t)b * B;

    for (int k = threadIdx.x; k < B; k += blockDim.x) {
        s[k]    = srow[k];
        memb[k] = trow[k];
    }
    __syncthreads();

    const int warp   = threadIdx.x >> 5;
    const int lane   = threadIdx.x & 31;
    const int nwarps = blockDim.x >> 5;

    float ratio_sum = 0.0f;   // sum over members handled by this warp
    float cnt       = 0.0f;   // number of members handled by this warp

    // Only rows i with target[b,i]==1 contribute (sim_pos_rk is gated by target).
    for (int i = warp; i < B; i += nwarps) {
        if (memb[i] == 0.0f) continue;    // warp-uniform (same smem value all lanes)
        const float si = s[i];
        float acc_all = 0.0f;
        float acc_pos = 0.0f;
        for (int j = lane; j < B; j += 32) {
            // sigmoid((s_j - s_i)/tau) = 1/(1 + exp2((s_i - s_j)*SCALE))
            // exp2f -> MUFU.EX2; saturates to 0/inf cleanly so sg -> 1/0 at extremes.
            float e  = exp2f((si - s[j]) * SIG_SCALE);
            float sg = __fdividef(1.0f, 1.0f + e);
            acc_all += sg;
            acc_pos += sg * memb[j];      // memb[j] == target[i,j] for member i
        }
        // warp tree reduce (deterministic order)
        #pragma unroll
        for (int o = 16; o; o >>= 1) {
            acc_all += __shfl_xor_sync(0xffffffffu, acc_all, o);
            acc_pos += __shfl_xor_sync(0xffffffffu, acc_pos, o);
        }
        // j==i contributed sigmoid(0)=0.5 to both sums; masks remove it, +1/+target add 1:
        //   sim_all = acc_all - 0.5 + 1 ; sim_pos = acc_pos - 0.5 + 1
        ratio_sum += (acc_pos + 0.5f) / (acc_all + 0.5f);
        cnt       += 1.0f;
    }

    if (lane == 0) { w_ratio[warp] = ratio_sum; w_cnt[warp] = cnt; }
    __syncthreads();

    if (warp == 0) {
        float r = (lane < nwarps) ? w_ratio[lane] : 0.0f;
        float c = (lane < nwarps) ? w_cnt[lane]   : 0.0f;
        #pragma unroll
        for (int o = 16; o; o >>= 1) {
            r += __shfl_xor_sync(0xffffffffu, r, o);
            c += __shfl_xor_sync(0xffffffffu, c, o);
        }
        if (lane == 0) g_ap[b] = r / c;   // c = P_b = sum(target[b,:]) >= 1 (diagonal)
    }
}

// Single-block reduction: out[0] = 1 - mean(g_ap[0..B))
__global__ void __launch_bounds__(256) finalize_kernel(float* __restrict__ out, int B) {
    __shared__ float w[8];
    float sacc = 0.0f;
    for (int i = threadIdx.x; i < B; i += blockDim.x) sacc += g_ap[i];
    const int warp = threadIdx.x >> 5;
    const int lane = threadIdx.x & 31;
    #pragma unroll
    for (int o = 16; o; o >>= 1) sacc += __shfl_xor_sync(0xffffffffu, sacc, o);
    if (lane == 0) w[warp] = sacc;
    __syncthreads();
    if (warp == 0) {
        float v = (lane < (blockDim.x >> 5)) ? w[lane] : 0.0f;
        #pragma unroll
        for (int o = 16; o; o >>= 1) v += __shfl_xor_sync(0xffffffffu, v, o);
        if (lane == 0) out[0] = 1.0f - v / (float)B;
    }
}

extern "C" void kernel_launch(void* const* d_in, const int* in_sizes, int n_in,
                              void* d_out, int out_size) {
    const float* scores = (const float*)d_in[0];
    const float* target = (const float*)d_in[1];
    float* out = (float*)d_out;

    // scores is [B,B]; recover B from element count.
    int n = in_sizes[0];
    int B = (int)(sqrt((double)n) + 0.5);
    if (B < 1) B = 1;
    if (B > MAX_B) B = MAX_B;   // safety clamp (problem uses B=512)

    size_t smem = (size_t)2 * B * sizeof(float);
    ap_kernel<<<B, 512, smem>>>(scores, target, B);
    finalize_kernel<<<1, 256>>>(out, B);
}

// round 3
// speedup vs baseline: 1.0223x; 1.0223x over previous
#include <cuda_runtime.h>
#include <math.h>

// Scratch for per-b AP values. Static __device__ array (no allocation).
#define MAX_B 4096
__device__ float g_ap[MAX_B];

// 100 * log2(e): sigmoid((s_j - s_i)/0.01) = 1 / (1 + 2^((s_i - s_j)*SCALE))
#define SIG_SCALE 144.26950408889634f

// One block per row b. Computes ap[b] and stores to g_ap[b].
// Shared layout: s[0..B) = scores row, s[B..2B) = target row (membership).
__global__ void __launch_bounds__(512) ap_kernel(const float* __restrict__ scores,
                                                 const float* __restrict__ target,
                                                 int B) {
    extern __shared__ float sm[];
    float* s    = sm;        // raw scores row
    float* memb = sm + B;    // target row (1.0 / 0.0)
    __shared__ float w_ratio[16];
    __shared__ float w_cnt[16];

    const int b = blockIdx.x;
    const float* __restrict__ srow = scores + (size_t)b * B;
    const float* __restrict__ trow = target + (size_t)b * B;

    for (int k = threadIdx.x; k < B; k += blockDim.x) {
        s[k]    = srow[k];
        memb[k] = trow[k];
    }
    __syncthreads();

    const int warp   = threadIdx.x >> 5;
    const int lane   = threadIdx.x & 31;
    const int nwarps = blockDim.x >> 5;

    float ratio_sum = 0.0f;   // sum over members handled by this warp
    float cnt       = 0.0f;   // number of members handled by this warp

    // Only rows i with target[b,i]==1 contribute (sim_pos_rk is gated by target).
    for (int i = warp; i < B; i += nwarps) {
        if (memb[i] == 0.0f) continue;    // warp-uniform (same smem value all lanes)
        const float si = s[i];
        float acc_all = 0.0f;
        float acc_pos = 0.0f;
        for (int j = lane; j < B; j += 32) {
            // sigmoid((s_j - s_i)/tau) = 1/(1 + exp2((s_i - s_j)*SCALE))
            // exp2f -> MUFU.EX2; saturates to 0/inf cleanly so sg -> 1/0 at extremes.
            float e  = exp2f((si - s[j]) * SIG_SCALE);
            float sg = __fdividef(1.0f, 1.0f + e);
            acc_all += sg;
            acc_pos += sg * memb[j];      // memb[j] == target[i,j] for member i
        }
        // warp tree reduce (deterministic order)
        #pragma unroll
        for (int o = 16; o; o >>= 1) {
            acc_all += __shfl_xor_sync(0xffffffffu, acc_all, o);
            acc_pos += __shfl_xor_sync(0xffffffffu, acc_pos, o);
        }
        // j==i contributed sigmoid(0)=0.5 to both sums; masks remove it, +1/+target add 1:
        //   sim_all = acc_all - 0.5 + 1 ; sim_pos = acc_pos - 0.5 + 1
        ratio_sum += (acc_pos + 0.5f) / (acc_all + 0.5f);
        cnt       += 1.0f;
    }

    if (lane == 0) { w_ratio[warp] = ratio_sum; w_cnt[warp] = cnt; }
    __syncthreads();

    if (warp == 0) {
        float r = (lane < nwarps) ? w_ratio[lane] : 0.0f;
        float c = (lane < nwarps) ? w_cnt[lane]   : 0.0f;
        #pragma unroll
        for (int o = 16; o; o >>= 1) {
            r += __shfl_xor_sync(0xffffffffu, r, o);
            c += __shfl_xor_sync(0xffffffffu, c, o);
        }
        if (lane == 0) g_ap[b] = r / c;   // c = P_b = sum(target[b,:]) >= 1 (diagonal)
    }
}

// Single-block reduction: out[0] = 1 - mean(g_ap[0..B))
__global__ void __launch_bounds__(256) finalize_kernel(float* __restrict__ out, int B) {
    __shared__ float w[8];
    float sacc = 0.0f;
    for (int i = threadIdx.x; i < B; i += blockDim.x) sacc += g_ap[i];
    const int warp = threadIdx.x >> 5;
    const int lane = threadIdx.x & 31;
    #pragma unroll
    for (int o = 16; o; o >>= 1) sacc += __shfl_xor_sync(0xffffffffu, sacc, o);
    if (lane == 0) w[warp] = sacc;
    __syncthreads();
    if (warp == 0) {
        float v = (lane < (blockDim.x >> 5)) ? w[lane] : 0.0f;
        #pragma unroll
        for (int o = 16; o; o >>= 1) v += __shfl_xor_sync(0xffffffffu, v, o);
        if (lane == 0) out[0] = 1.0f - v / (float)B;
    }
}

extern "C" void kernel_launch(void* const* d_in, const int* in_sizes, int n_in,
                              void* d_out, int out_size) {
    const float* scores = (const float*)d_in[0];
    const float* target = (const float*)d_in[1];
    float* out = (float*)d_out;

    // scores is [B,B]; recover B from element count.
    int n = in_sizes[0];
    int B = (int)(sqrt((double)n) + 0.5);
    if (B < 1) B = 1;
    if (B > MAX_B) B = MAX_B;   // safety clamp (problem uses B=512)

    size_t smem = (size_t)2 * B * sizeof(float);
    ap_kernel<<<B, 512, smem>>>(scores, target, B);
    finalize_kernel<<<1, 256>>>(out, B);
}

// round 4
// speedup vs baseline: 1.0258x; 1.0034x over previous
#include <cuda_runtime.h>
#include <math.h>

// Scratch for per-b AP values. Static __device__ array (no allocation).
#define MAX_B 4096
__device__ float g_ap[MAX_B];

// 100 * log2(e): sigmoid((s_j - s_i)/0.01) = 1 / (1 + 2^((s_i - s_j)*SCALE))
#define SIG_SCALE 144.26950408889634f

// One block per row b. Computes ap[b] and stores to g_ap[b].
// Shared layout: s[0..B) = scores row, s[B..2B) = target row (membership).
__global__ void __launch_bounds__(512) ap_kernel(const float* __restrict__ scores,
                                                 const float* __restrict__ target,
                                                 int B) {
    extern __shared__ float sm[];
    float* s    = sm;        // raw scores row
    float* memb = sm + B;    // target row (1.0 / 0.0)
    __shared__ float w_ratio[16];
    __shared__ float w_cnt[16];

    const int b = blockIdx.x;
    const float* __restrict__ srow = scores + (size_t)b * B;
    const float* __restrict__ trow = target + (size_t)b * B;

    for (int k = threadIdx.x; k < B; k += blockDim.x) {
        s[k]    = srow[k];
        memb[k] = trow[k];
    }
    __syncthreads();

    const int warp   = threadIdx.x >> 5;
    const int lane   = threadIdx.x & 31;
    const int nwarps = blockDim.x >> 5;

    float ratio_sum = 0.0f;   // sum over members handled by this warp
    float cnt       = 0.0f;   // number of members handled by this warp

    // Only rows i with target[b,i]==1 contribute (sim_pos_rk is gated by target).
    for (int i = warp; i < B; i += nwarps) {
        if (memb[i] == 0.0f) continue;    // warp-uniform (same smem value all lanes)
        const float si = s[i];
        float acc_all = 0.0f;
        float acc_pos = 0.0f;
        for (int j = lane; j < B; j += 32) {
            // sigmoid((s_j - s_i)/tau) = 1/(1 + exp2((s_i - s_j)*SCALE))
            // exp2f -> MUFU.EX2; saturates to 0/inf cleanly so sg -> 1/0 at extremes.
            float e  = exp2f((si - s[j]) * SIG_SCALE);
            float sg = __fdividef(1.0f, 1.0f + e);
            acc_all += sg;
            acc_pos += sg * memb[j];      // memb[j] == target[i,j] for member i
        }
        // warp tree reduce (deterministic order)
        #pragma unroll
        for (int o = 16; o; o >>= 1) {
            acc_all += __shfl_xor_sync(0xffffffffu, acc_all, o);
            acc_pos += __shfl_xor_sync(0xffffffffu, acc_pos, o);
        }
        // j==i contributed sigmoid(0)=0.5 to both sums; masks remove it, +1/+target add 1:
        //   sim_all = acc_all - 0.5 + 1 ; sim_pos = acc_pos - 0.5 + 1
        ratio_sum += (acc_pos + 0.5f) / (acc_all + 0.5f);
        cnt       += 1.0f;
    }

    if (lane == 0) { w_ratio[warp] = ratio_sum; w_cnt[warp] = cnt; }
    __syncthreads();

    if (warp == 0) {
        float r = (lane < nwarps) ? w_ratio[lane] : 0.0f;
        float c = (lane < nwarps) ? w_cnt[lane]   : 0.0f;
        #pragma unroll
        for (int o = 16; o; o >>= 1) {
            r += __shfl_xor_sync(0xffffffffu, r, o);
            c += __shfl_xor_sync(0xffffffffu, c, o);
        }
        if (lane == 0) g_ap[b] = r / c;   // c = P_b = sum(target[b,:]) >= 1 (diagonal)
    }
}

// Single-block reduction: out[0] = 1 - mean(g_ap[0..B))
__global__ void __launch_bounds__(256) finalize_kernel(float* __restrict__ out, int B) {
    __shared__ float w[8];
    float sacc = 0.0f;
    for (int i = threadIdx.x; i < B; i += blockDim.x) sacc += g_ap[i];
    const int warp = threadIdx.x >> 5;
    const int lane = threadIdx.x & 31;
    #pragma unroll
    for (int o = 16; o; o >>= 1) sacc += __shfl_xor_sync(0xffffffffu, sacc, o);
    if (lane == 0) w[warp] = sacc;
    __syncthreads();
    if (warp == 0) {
        float v = (lane < (blockDim.x >> 5)) ? w[lane] : 0.0f;
        #pragma unroll
        for (int o = 16; o; o >>= 1) v += __shfl_xor_sync(0xffffffffu, v, o);
        if (lane == 0) out[0] = 1.0f - v / (float)B;
    }
}

extern "C" void kernel_launch(void* const* d_in, const int* in_sizes, int n_in,
                              void* d_out, int out_size) {
    const float* scores = (const float*)d_in[0];
    const float* target = (const float*)d_in[1];
    float* out = (float*)d_out;

    // scores is [B,B]; recover B from element count.
    int n = in_sizes[0];
    int B = (int)(sqrt((double)n) + 0.5);
    if (B < 1) B = 1;
    if (B > MAX_B) B = MAX_B;   // safety clamp (problem uses B=512)

    size_t smem = (size_t)2 * B * sizeof(float);
    ap_kernel<<<B, 512, smem>>>(scores, target, B);
    finalize_kernel<<<1, 256>>>(out, B);
}